// round 15
// baseline (speedup 1.0000x reference)
#include <cuda_runtime.h>
#include <math.h>
#include <stdint.h>

#define BB 32
#define TT_LEN 2048
#define DD 512
#define NH 1024        // complex FFT length (real length 2048)
#define KSEL 16
#define TTILE 256
#define NM (TT_LEN / TTILE)   // 8
#define PI_D 3.14159265358979323846

// padded smem indexing (pad every 16 float2)
#define IDX(i) ((i) + ((i) >> 4))
#define PADN (NH + NH / 16)   // 1088
#define SPITCH 2184           // staging float pitch per channel (skew 8 mod 32)

// ---------------- device scratch ------------------------------------------
__device__ float2 d_twf[256];        // w   = exp(-2pi i j / 1024)
__device__ float2 d_twf2[256];       // w^2
__device__ float2 d_twf3[256];       // w^3
__device__ float2 d_twu[NH];         // untangle twiddles exp(-2pi i k / 2048)
__device__ float  d_cwT[NH];         // cos(omega_k)
__device__ float  d_swT[NH];         // sin(omega_k)
__device__ float  d_eT[NH];          // -4 sin^2(omega_k/2)
__device__ float2 d_rot0[NM * NH];   // e^{i omega_k * TTILE * m}
__device__ float  d_c0[BB * DD * KSEL];
__device__ float  d_s0[BB * DD * KSEL];
__device__ int    d_kix[BB * DD * KSEL];

// ---------------- packed f32x2 helpers ------------------------------------
typedef unsigned long long u64;
__device__ __forceinline__ u64 pk(float lo, float hi) {
    u64 r; asm("mov.b64 %0,{%1,%2};" : "=l"(r) : "f"(lo), "f"(hi)); return r;
}
__device__ __forceinline__ void upk(u64 v, float& lo, float& hi) {
    asm("mov.b64 {%0,%1},%2;" : "=f"(lo), "=f"(hi) : "l"(v));
}
#define F2ADD(d,a,b)   asm("add.rn.f32x2 %0,%1,%2;"    : "=l"(d) : "l"(a), "l"(b))
#define F2FMA(d,a,b,c) asm("fma.rn.f32x2 %0,%1,%2,%3;" : "=l"(d) : "l"(a), "l"(b), "l"(c))

// ---------------- init: fp32 sincospi (args are angle/pi) -----------------
__global__ void init_tables() {
    int gid = blockIdx.x * blockDim.x + threadIdx.x;   // 47*256 = 12032
    const double OMS = 2.0 / ((double)TT_LEN * (double)(TT_LEN - 1)); // omega/pi per k
    if (gid < 256) {
        float s, c; sincospif(-2.0f * (float)gid / (float)NH, &s, &c);
        d_twf[gid] = make_float2(c, s);
    } else if (gid < 512) {
        int j = gid - 256;
        float s, c; sincospif(-4.0f * (float)j / (float)NH, &s, &c);
        d_twf2[j] = make_float2(c, s);
    } else if (gid < 768) {
        int j = gid - 512;
        float s, c; sincospif(-6.0f * (float)j / (float)NH, &s, &c);
        d_twf3[j] = make_float2(c, s);
    } else if (gid < 1792) {
        int k = gid - 768;
        float s, c; sincospif(-(float)k / (float)NH, &s, &c);
        d_twu[k] = make_float2(c, s);
    } else if (gid < 2816) {
        int k = gid - 1792;
        double a = OMS * (double)k;             // omega/pi
        float s, c; sincospif((float)a, &s, &c);
        d_cwT[k] = c;  d_swT[k] = s;
    } else if (gid < 3840) {
        int k = gid - 2816;
        double a = 0.5 * OMS * (double)k;
        float sh, ch; sincospif((float)a, &sh, &ch);
        d_eT[k] = -4.0f * sh * sh;
    } else if (gid < 3840 + NM * NH) {
        int e = gid - 3840;
        int m = e >> 10, k = e & (NH - 1);
        double a = OMS * (double)k * (double)(TTILE * m);   // angle/pi
        a = a - 2.0 * floor(a * 0.5);                       // reduce mod 2
        float s, c; sincospif((float)a, &s, &c);
        d_rot0[e] = make_float2(c, s);
    }
}

__device__ __forceinline__ float2 cmulf(float2 a, float2 b) {
    return make_float2(a.x * b.x - a.y * b.y, a.x * b.y + a.y * b.x);
}
__device__ __forceinline__ float2 cadd(float2 a, float2 b) { return make_float2(a.x + b.x, a.y + b.y); }
__device__ __forceinline__ float2 csub(float2 a, float2 b) { return make_float2(a.x - b.x, a.y - b.y); }

__device__ __forceinline__ void bfly4(float2 a, float2 b, float2 c, float2 d,
                                      float2 w1, float2 w2, float2 w3,
                                      float2& o0, float2& o1, float2& o2, float2& o3) {
    float2 t0 = cadd(a, c);
    float2 t1 = csub(a, c);
    float2 t2 = cadd(b, d);
    float2 e  = csub(b, d);
    float2 t3 = make_float2(e.y, -e.x);   // -i*(b-d)
    o0 = cadd(t0, t2);
    o1 = cmulf(w1, cadd(t1, t3));
    o2 = cmulf(w2, csub(t0, t2));
    o3 = cmulf(w3, csub(t1, t3));
}

// Twiddle-free final butterfly (M=256 pass): bins {j, j+256, j+512, j+768}.
__device__ __forceinline__ void bfly4_id(float2 a, float2 b, float2 c, float2 d,
                                         float2& o0, float2& o1, float2& o2, float2& o3) {
    float2 t0 = cadd(a, c);
    float2 t1 = csub(a, c);
    float2 t2 = cadd(b, d);
    float2 e  = csub(b, d);
    float2 t3 = make_float2(e.y, -e.x);
    o0 = cadd(t0, t2);
    o1 = cadd(t1, t3);
    o2 = csub(t0, t2);
    o3 = csub(t1, t3);
}

// Untangle from register values: real-FFT bin k from Z[k], Z[NH-k].
__device__ __forceinline__ float2 untangle_v(float2 Zk, float2 Znk, int k) {
    float Ex = 0.5f * (Zk.x + Znk.x), Ey = 0.5f * (Zk.y - Znk.y);
    float Ox = 0.5f * (Zk.y + Znk.y), Oy = -0.5f * (Zk.x - Znk.x);
    float2 e = d_twu[k];
    float eox = e.x * Ox - e.y * Oy;
    float eoy = e.x * Oy + e.y * Ox;
    return make_float2(Ex + eox, Ey + eoy);
}

// Magnitudes of real-FFT bins k and NH-k from Z[k], Z[NH-k] (registers).
__device__ __forceinline__ void mag_pair_v(float2 Zk, float2 Znk, int k,
                                           unsigned& mk, unsigned& mnk) {
    float Ex = 0.5f * (Zk.x + Znk.x), Ey = 0.5f * (Zk.y - Znk.y);
    float Ox = 0.5f * (Zk.y + Znk.y), Oy = -0.5f * (Zk.x - Znk.x);
    float2 e = d_twu[k];
    float eox = e.x * Ox - e.y * Oy;
    float eoy = e.x * Oy + e.y * Ox;
    float px = Ex + eox, py = Ey + eoy;
    float qx = Ex - eox, qy = Ey - eoy;
    mk  = __float_as_uint(px * px + py * py);
    mnk = __float_as_uint(qx * qx + qy * qy);
}

// ---------------- analysis: fused transpose + FFT, 4 channels / block -----
__global__ __launch_bounds__(256, 4) void analyze(const float* __restrict__ x) {
    __shared__ float2   buf[4][PADN];
    __shared__ unsigned cand_v[4][8 * KSEL];
    __shared__ int      cand_k[4][8 * KSEL];
    __shared__ int      sel[4][KSEL];

    const int tid = threadIdx.x;
    const int u   = tid & 63;
    const int c   = tid >> 6;
    float2* B = buf[c];
    float*  Fs = (float*)(&buf[0][0]);
    const int b4  = blockIdx.x >> 7;                    // batch
    const int col = (blockIdx.x & 127) * 2;             // float2 column base

    // ---- load + transpose into staging ----
    {
        const float2* xr = (const float2*)x;
        const int dp = tid & 1;
        const int tl = tid >> 1;
        size_t rowbase = ((size_t)b4 * TT_LEN) * 256 + (size_t)(col + dp);
#pragma unroll
        for (int it = 0; it < 16; it++) {
            int t = tl + 128 * it;
            float2 v = xr[rowbase + (size_t)t * 256];
            Fs[(2 * dp)     * SPITCH + t] = v.x;
            Fs[(2 * dp + 1) * SPITCH + t] = v.y;
        }
    }
    __syncthreads();

    // ---- stage pair A: pass M=1 then M=4, fused ----
    {
        const float2* Sc = (const float2*)(Fs + c * SPITCH);
        float2 V[4][4];
#pragma unroll
        for (int qq = 0; qq < 4; qq++) {
            int t = u + 64 * qq;
            float2 a  = Sc[t];
            float2 b  = Sc[t + 256];
            float2 cc = Sc[t + 512];
            float2 dd = Sc[t + 768];
            bfly4(a, b, cc, dd, d_twf[t], d_twf2[t], d_twf3[t],
                  V[qq][0], V[qq][1], V[qq][2], V[qq][3]);
        }
        __syncthreads();

        float2 w1 = d_twf[4 * u], w2 = d_twf2[4 * u], w3 = d_twf3[4 * u];
#pragma unroll
        for (int lam = 0; lam < 4; lam++) {
            float2 o0, o1, o2, o3;
            bfly4(V[0][lam], V[1][lam], V[2][lam], V[3][lam], w1, w2, w3,
                  o0, o1, o2, o3);
            B[IDX(16 * u +  0 + lam)] = o0;
            B[IDX(16 * u +  4 + lam)] = o1;
            B[IDX(16 * u +  8 + lam)] = o2;
            B[IDX(16 * u + 12 + lam)] = o3;
        }
    }
    __syncthreads();

    // ---- stage pair B: pass M=16 then M=64, fused ----
    {
        const int ub = u & ~15;
        float2 V[4][4];
#pragma unroll
        for (int qq = 0; qq < 4; qq++) {
            float2 r0 = B[IDX(u + 64 * qq)];
            float2 r1 = B[IDX(u + 64 * qq + 256)];
            float2 r2 = B[IDX(u + 64 * qq + 512)];
            float2 r3 = B[IDX(u + 64 * qq + 768)];
            int j = ub + 64 * qq;
            bfly4(r0, r1, r2, r3, d_twf[j], d_twf2[j], d_twf3[j],
                  V[qq][0], V[qq][1], V[qq][2], V[qq][3]);
        }
        __syncthreads();

        int j2 = 4 * ub;
        float2 w1 = d_twf[j2], w2 = d_twf2[j2], w3 = d_twf3[j2];
        int basei = 16 * ub + (u & 15);
#pragma unroll
        for (int lam = 0; lam < 4; lam++) {
            float2 o0, o1, o2, o3;
            bfly4(V[0][lam], V[1][lam], V[2][lam], V[3][lam], w1, w2, w3,
                  o0, o1, o2, o3);
            B[IDX(basei + 16 * lam +   0)] = o0;
            B[IDX(basei + 16 * lam +  64)] = o1;
            B[IDX(basei + 16 * lam + 128)] = o2;
            B[IDX(basei + 16 * lam + 192)] = o3;
        }
    }
    __syncthreads();
    // B now holds PRE-final-pass data; final (twiddle-free) pass is fused
    // into the mag phase below and recomputed at emit. B is not written again.

    // ---- fused final pass + mags: two butterflies in registers ----
    // Thread tid owns real-bin pairs (tid, 1024-tid) and (tid+256, 768-tid);
    // tid==0 owns (512) and (256, 768). Exact cover of bins 1..1023.
    unsigned uv[4][4];
    int      kv[4][4];
    const int jp = (256 - tid) & 255;
#pragma unroll
    for (int cc = 0; cc < 4; cc++) {
        const float2* Z = buf[cc];
        float2 Ya0, Ya1, Ya2, Ya3, Yb0, Yb1, Yb2, Yb3;
        {
            float2 a0 = Z[IDX(tid)],       a1 = Z[IDX(tid + 256)];
            float2 a2 = Z[IDX(tid + 512)], a3 = Z[IDX(tid + 768)];
            bfly4_id(a0, a1, a2, a3, Ya0, Ya1, Ya2, Ya3);
        }
        {
            float2 a0 = Z[IDX(jp)],       a1 = Z[IDX(jp + 256)];
            float2 a2 = Z[IDX(jp + 512)], a3 = Z[IDX(jp + 768)];
            bfly4_id(a0, a1, a2, a3, Yb0, Yb1, Yb2, Yb3);
        }
        unsigned m0, m1, m2, m3;
        int b0, b1, b2, b3;
        if (tid == 0) {
            // bin 512 (self-paired) + pair (256, 768)
            mag_pair_v(Ya2, Ya2, 512, m0, m1);
            m1 = 0u;  b0 = 512;  b1 = 512;
            mag_pair_v(Ya1, Ya3, 256, m2, m3);
            b2 = 256; b3 = 768;
        } else {
            mag_pair_v(Ya0, Yb3, tid, m0, m1);          // (tid, 1024-tid)
            b0 = tid;        b1 = NH - tid;
            mag_pair_v(Ya1, Yb2, tid + 256, m2, m3);    // (tid+256, 768-tid)
            b2 = tid + 256;  b3 = 768 - tid;
        }
#define CSWP(a, b, ka, kb) if (a < b) { unsigned tu = a; a = b; b = tu; int tk = ka; ka = kb; kb = tk; }
        CSWP(m0, m1, b0, b1)
        CSWP(m2, m3, b2, b3)
        CSWP(m0, m2, b0, b2)
        CSWP(m1, m3, b1, b3)
        CSWP(m1, m2, b1, b2)
#undef CSWP
        uv[cc][0] = m0; uv[cc][1] = m1; uv[cc][2] = m2; uv[cc][3] = m3;
        kv[cc][0] = b0; kv[cc][1] = b1; kv[cc][2] = b2; kv[cc][3] = b3;
    }

    const int lane = tid & 31;
    const int warp = tid >> 5;
    const unsigned FULL = 0xffffffffu;

    // phase 1: per-warp top-16, 4 independent REDUX streams
    for (int r = 0; r < KSEL; r++) {
#pragma unroll
        for (int cc = 0; cc < 4; cc++) {
            unsigned mx = __reduce_max_sync(FULL, uv[cc][0]);
            unsigned ball = __ballot_sync(FULL, uv[cc][0] == mx);
            int wl = __ffs((int)ball) - 1;
            if (lane == wl) {
                cand_v[cc][warp * KSEL + r] = uv[cc][0];
                cand_k[cc][warp * KSEL + r] = kv[cc][0];
                uv[cc][0] = uv[cc][1]; kv[cc][0] = kv[cc][1];
                uv[cc][1] = uv[cc][2]; kv[cc][1] = kv[cc][2];
                uv[cc][2] = uv[cc][3]; kv[cc][2] = kv[cc][3];
                uv[cc][3] = 0u;
            }
        }
    }
    __syncthreads();

    // phase 2: warps 0-3 merge channels 0-3 in parallel
    if (warp < 4) {
        const int cc = warp;
        int ptr = 0, curk = 0;
        unsigned hv = 0u;
        if (lane < 8) { hv = cand_v[cc][lane * KSEL]; curk = cand_k[cc][lane * KSEL]; }
        for (int r = 0; r < KSEL; r++) {
            unsigned mx = __reduce_max_sync(FULL, hv);
            unsigned ball = __ballot_sync(FULL, hv == mx);
            int wl = __ffs((int)ball) - 1;
            int kwin = __shfl_sync(FULL, curk, wl);
            if (lane == 0) sel[cc][r] = kwin;
            if (lane == wl) {
                ptr++;
                if (ptr < KSEL) {
                    hv = cand_v[cc][lane * KSEL + ptr];
                    curk = cand_k[cc][lane * KSEL + ptr];
                } else {
                    hv = 0u;
                }
            }
        }
    }
    __syncthreads();

    // emit: recompute the two final butterflies for each selected bin
    if (warp < 4 && lane < KSEL) {
        const float2* Z = buf[warp];
        int k  = sel[warp][lane];
        int nk = (NH - k) & (NH - 1);      // k=512 -> 512; k never 0
        float2 Zk, Znk;
        {
            int j = k & 255;
            float2 a0 = Z[IDX(j)],       a1 = Z[IDX(j + 256)];
            float2 a2 = Z[IDX(j + 512)], a3 = Z[IDX(j + 768)];
            float2 y0, y1, y2, y3;
            bfly4_id(a0, a1, a2, a3, y0, y1, y2, y3);
            int q = k >> 8;
            Zk = (q == 0) ? y0 : (q == 1) ? y1 : (q == 2) ? y2 : y3;
        }
        {
            int j = nk & 255;
            float2 a0 = Z[IDX(j)],       a1 = Z[IDX(j + 256)];
            float2 a2 = Z[IDX(j + 512)], a3 = Z[IDX(j + 768)];
            float2 y0, y1, y2, y3;
            bfly4_id(a0, a1, a2, a3, y0, y1, y2, y3);
            int q = nk >> 8;
            Znk = (q == 0) ? y0 : (q == 1) ? y1 : (q == 2) ? y2 : y3;
        }
        float2 Xk = untangle_v(Zk, Znk, k);
        int base = ((b4 * DD) + ((blockIdx.x & 127) * 4 + warp)) * KSEL + lane;
        d_c0[base]  = Xk.x;
        d_s0[base]  = Xk.y;
        d_kix[base] = k;
    }
}

// ---------------- synthesis: packed-f32x2 Reinsch oscillator --------------
__global__ __launch_bounds__(128, 7) void synth(float* __restrict__ out) {
    const int b  = blockIdx.z;
    const int d  = blockIdx.y * 128 + threadIdx.x;
    const int m  = blockIdx.x;
    const int base = (b * DD + d) * KSEL;
    const float2* rot = d_rot0 + m * NH;

    float ys[KSEL], dss[KSEL], es[KSEL];
#pragma unroll
    for (int r = 0; r < KSEL; r++) {
        int    k  = d_kix[base + r];
        float  c0 = d_c0[base + r];
        float  s0 = d_s0[base + r];
        float2 rk = rot[k];
        float  y  = fmaf(c0, rk.x, -s0 * rk.y);
        float  sn = fmaf(c0, rk.y,  s0 * rk.x);
        float  cw = d_cwT[k];
        float  sw = d_swT[k];
        float  yp = fmaf(y, cw, sn * sw);
        ys[r]  = y;
        dss[r] = y - yp;
        es[r]  = d_eT[k];
    }

    u64 Y[8], D[8], E[8];
#pragma unroll
    for (int p = 0; p < 8; p++) {
        Y[p] = pk(ys[2 * p],  ys[2 * p + 1]);
        D[p] = pk(dss[2 * p], dss[2 * p + 1]);
        E[p] = pk(es[2 * p],  es[2 * p + 1]);
    }

    float* po = out + ((size_t)b * TT_LEN + m * TTILE) * DD + d;
#pragma unroll 4
    for (int tt = 0; tt < TTILE; tt++) {
        u64 q0, q1, q2, q3;
        F2ADD(q0, Y[0], Y[1]);
        F2ADD(q1, Y[2], Y[3]);
        F2ADD(q2, Y[4], Y[5]);
        F2ADD(q3, Y[6], Y[7]);
        F2ADD(q0, q0, q1);
        F2ADD(q2, q2, q3);
        F2ADD(q0, q0, q2);
        float lo, hi;
        upk(q0, lo, hi);
        po[(size_t)tt * DD] = lo + hi;

#pragma unroll
        for (int p = 0; p < 8; p++) {
            F2FMA(D[p], E[p], Y[p], D[p]);
            F2ADD(Y[p], Y[p], D[p]);
        }
    }
}

// ---------------- launch ----------------------------------------------------
extern "C" void kernel_launch(void* const* d_in, const int* in_sizes, int n_in,
                              void* d_out, int out_size) {
    const float* x = (const float*)d_in[0];
    float* out = (float*)d_out;

    init_tables<<<47, 256>>>();
    analyze<<<BB * DD / 4, 256>>>(x);
    synth<<<dim3(NM, DD / 128, BB), 128>>>(out);
}

// round 16
// speedup vs baseline: 1.0393x; 1.0393x over previous
#include <cuda_runtime.h>
#include <math.h>
#include <stdint.h>

#define BB 32
#define TT_LEN 2048
#define DD 512
#define NH 1024        // complex FFT length (real length 2048)
#define KSEL 16
#define TTILE 256
#define NM (TT_LEN / TTILE)   // 8
#define PI_D 3.14159265358979323846

// padded smem indexing (pad every 16 float2)
#define IDX(i) ((i) + ((i) >> 4))
#define PADN (NH + NH / 16)   // 1088
#define SPITCH 2184           // staging float pitch per channel (skew 8 mod 32)

// ---------------- device scratch ------------------------------------------
__device__ float2 d_twf[256];        // w   = exp(-2pi i j / 1024)
__device__ float2 d_twf2[256];       // w^2
__device__ float2 d_twf3[256];       // w^3
__device__ float2 d_twu[NH];         // untangle twiddles exp(-2pi i k / 2048)
__device__ float  d_cwT[NH];         // cos(omega_k)
__device__ float  d_swT[NH];         // sin(omega_k)
__device__ float  d_eT[NH];          // -4 sin^2(omega_k/2)
__device__ float2 d_rot0[NM * NH];   // e^{i omega_k * TTILE * m}
// coefficient arrays, TRANSPOSED layout [b][r][d] for coalesced synth loads
__device__ float  d_c0[BB * KSEL * DD];
__device__ float  d_s0[BB * KSEL * DD];
__device__ float  d_cw2[BB * KSEL * DD];
__device__ float  d_sw2[BB * KSEL * DD];
__device__ float  d_e2[BB * KSEL * DD];
__device__ int    d_kix[BB * KSEL * DD];

// ---------------- packed f32x2 helpers ------------------------------------
typedef unsigned long long u64;
__device__ __forceinline__ u64 pk(float lo, float hi) {
    u64 r; asm("mov.b64 %0,{%1,%2};" : "=l"(r) : "f"(lo), "f"(hi)); return r;
}
__device__ __forceinline__ void upk(u64 v, float& lo, float& hi) {
    asm("mov.b64 {%0,%1},%2;" : "=f"(lo), "=f"(hi) : "l"(v));
}
#define F2ADD(d,a,b)   asm("add.rn.f32x2 %0,%1,%2;"    : "=l"(d) : "l"(a), "l"(b))
#define F2FMA(d,a,b,c) asm("fma.rn.f32x2 %0,%1,%2,%3;" : "=l"(d) : "l"(a), "l"(b), "l"(c))

// ---------------- init: fp32 sincospi (args are angle/pi) -----------------
__global__ void init_tables() {
    int gid = blockIdx.x * blockDim.x + threadIdx.x;   // 47*256 = 12032
    const double OMS = 2.0 / ((double)TT_LEN * (double)(TT_LEN - 1)); // omega/pi per k
    if (gid < 256) {
        float s, c; sincospif(-2.0f * (float)gid / (float)NH, &s, &c);
        d_twf[gid] = make_float2(c, s);
    } else if (gid < 512) {
        int j = gid - 256;
        float s, c; sincospif(-4.0f * (float)j / (float)NH, &s, &c);
        d_twf2[j] = make_float2(c, s);
    } else if (gid < 768) {
        int j = gid - 512;
        float s, c; sincospif(-6.0f * (float)j / (float)NH, &s, &c);
        d_twf3[j] = make_float2(c, s);
    } else if (gid < 1792) {
        int k = gid - 768;
        float s, c; sincospif(-(float)k / (float)NH, &s, &c);
        d_twu[k] = make_float2(c, s);
    } else if (gid < 2816) {
        int k = gid - 1792;
        double a = OMS * (double)k;             // omega/pi
        float s, c; sincospif((float)a, &s, &c);
        d_cwT[k] = c;  d_swT[k] = s;
    } else if (gid < 3840) {
        int k = gid - 2816;
        double a = 0.5 * OMS * (double)k;
        float sh, ch; sincospif((float)a, &sh, &ch);
        d_eT[k] = -4.0f * sh * sh;
    } else if (gid < 3840 + NM * NH) {
        int e = gid - 3840;
        int m = e >> 10, k = e & (NH - 1);
        double a = OMS * (double)k * (double)(TTILE * m);   // angle/pi
        a = a - 2.0 * floor(a * 0.5);                       // reduce mod 2
        float s, c; sincospif((float)a, &s, &c);
        d_rot0[e] = make_float2(c, s);
    }
}

__device__ __forceinline__ float2 cmulf(float2 a, float2 b) {
    return make_float2(a.x * b.x - a.y * b.y, a.x * b.y + a.y * b.x);
}
__device__ __forceinline__ float2 cadd(float2 a, float2 b) { return make_float2(a.x + b.x, a.y + b.y); }
__device__ __forceinline__ float2 csub(float2 a, float2 b) { return make_float2(a.x - b.x, a.y - b.y); }

__device__ __forceinline__ void bfly4(float2 a, float2 b, float2 c, float2 d,
                                      float2 w1, float2 w2, float2 w3,
                                      float2& o0, float2& o1, float2& o2, float2& o3) {
    float2 t0 = cadd(a, c);
    float2 t1 = csub(a, c);
    float2 t2 = cadd(b, d);
    float2 e  = csub(b, d);
    float2 t3 = make_float2(e.y, -e.x);   // -i*(b-d)
    o0 = cadd(t0, t2);
    o1 = cmulf(w1, cadd(t1, t3));
    o2 = cmulf(w2, csub(t0, t2));
    o3 = cmulf(w3, csub(t1, t3));
}

__device__ __forceinline__ float2 untangle(const float2* Z, int k) {
    float2 A  = Z[IDX(k)];
    float2 Bv = Z[IDX(NH - k)];
    float2 Bc = make_float2(Bv.x, -Bv.y);
    float2 E  = make_float2(0.5f * (A.x + Bc.x), 0.5f * (A.y + Bc.y));
    float2 Od = make_float2(A.x - Bc.x, A.y - Bc.y);
    float2 O  = make_float2(0.5f * Od.y, -0.5f * Od.x);
    float2 eo = cmulf(d_twu[k], O);
    return make_float2(E.x + eo.x, E.y + eo.y);
}

// Conjugate-pair magnitudes: one load pair -> |X(k)|^2 and |X(NH-k)|^2.
__device__ __forceinline__ void mag_pair(const float2* Z, int k,
                                         unsigned& mk, unsigned& mnk) {
    float2 A  = Z[IDX(k)];
    float2 Bv = Z[IDX(NH - k)];
    float Ex = 0.5f * (A.x + Bv.x), Ey = 0.5f * (A.y - Bv.y);
    float Ox = 0.5f * (A.y + Bv.y), Oy = -0.5f * (A.x - Bv.x);
    float2 e = d_twu[k];
    float eox = e.x * Ox - e.y * Oy;
    float eoy = e.x * Oy + e.y * Ox;
    float px = Ex + eox, py = Ey + eoy;
    float qx = Ex - eox, qy = Ey - eoy;
    mk  = __float_as_uint(px * px + py * py);
    mnk = __float_as_uint(qx * qx + qy * qy);
}

// ---------------- analysis: fused transpose + FFT, 4 channels / block -----
__global__ __launch_bounds__(256, 4) void analyze(const float* __restrict__ x) {
    __shared__ float2   buf[4][PADN];
    __shared__ unsigned cand_v[4][8 * KSEL];
    __shared__ int      cand_k[4][8 * KSEL];
    __shared__ int      sel[4][KSEL];

    const int tid = threadIdx.x;
    const int u   = tid & 63;
    const int c   = tid >> 6;
    float2* B = buf[c];
    float*  Fs = (float*)(&buf[0][0]);
    const int b4  = blockIdx.x >> 7;                    // batch
    const int col = (blockIdx.x & 127) * 2;             // float2 column base

    // ---- load + transpose into staging ----
    {
        const float2* xr = (const float2*)x;
        const int dp = tid & 1;
        const int tl = tid >> 1;
        size_t rowbase = ((size_t)b4 * TT_LEN) * 256 + (size_t)(col + dp);
#pragma unroll
        for (int it = 0; it < 16; it++) {
            int t = tl + 128 * it;
            float2 v = xr[rowbase + (size_t)t * 256];
            Fs[(2 * dp)     * SPITCH + t] = v.x;
            Fs[(2 * dp + 1) * SPITCH + t] = v.y;
        }
    }
    __syncthreads();

    // ---- stage pair A: pass M=1 then M=4, fused ----
    {
        const float2* Sc = (const float2*)(Fs + c * SPITCH);
        float2 V[4][4];
#pragma unroll
        for (int qq = 0; qq < 4; qq++) {
            int t = u + 64 * qq;
            float2 a  = Sc[t];
            float2 b  = Sc[t + 256];
            float2 cc = Sc[t + 512];
            float2 dd = Sc[t + 768];
            bfly4(a, b, cc, dd, d_twf[t], d_twf2[t], d_twf3[t],
                  V[qq][0], V[qq][1], V[qq][2], V[qq][3]);
        }
        __syncthreads();

        float2 w1 = d_twf[4 * u], w2 = d_twf2[4 * u], w3 = d_twf3[4 * u];
#pragma unroll
        for (int lam = 0; lam < 4; lam++) {
            float2 o0, o1, o2, o3;
            bfly4(V[0][lam], V[1][lam], V[2][lam], V[3][lam], w1, w2, w3,
                  o0, o1, o2, o3);
            B[IDX(16 * u +  0 + lam)] = o0;
            B[IDX(16 * u +  4 + lam)] = o1;
            B[IDX(16 * u +  8 + lam)] = o2;
            B[IDX(16 * u + 12 + lam)] = o3;
        }
    }
    __syncthreads();

    // ---- stage pair B: pass M=16 then M=64, fused ----
    {
        const int ub = u & ~15;
        float2 V[4][4];
#pragma unroll
        for (int qq = 0; qq < 4; qq++) {
            float2 r0 = B[IDX(u + 64 * qq)];
            float2 r1 = B[IDX(u + 64 * qq + 256)];
            float2 r2 = B[IDX(u + 64 * qq + 512)];
            float2 r3 = B[IDX(u + 64 * qq + 768)];
            int j = ub + 64 * qq;
            bfly4(r0, r1, r2, r3, d_twf[j], d_twf2[j], d_twf3[j],
                  V[qq][0], V[qq][1], V[qq][2], V[qq][3]);
        }
        __syncthreads();

        int j2 = 4 * ub;
        float2 w1 = d_twf[j2], w2 = d_twf2[j2], w3 = d_twf3[j2];
        int basei = 16 * ub + (u & 15);
#pragma unroll
        for (int lam = 0; lam < 4; lam++) {
            float2 o0, o1, o2, o3;
            bfly4(V[0][lam], V[1][lam], V[2][lam], V[3][lam], w1, w2, w3,
                  o0, o1, o2, o3);
            B[IDX(basei + 16 * lam +   0)] = o0;
            B[IDX(basei + 16 * lam +  64)] = o1;
            B[IDX(basei + 16 * lam + 128)] = o2;
            B[IDX(basei + 16 * lam + 192)] = o3;
        }
    }
    __syncthreads();

    // ---- final pass M=256: per-thread in place ----
#pragma unroll
    for (int qq = 0; qq < 4; qq++) {
        int t = u + 64 * qq;
        float2 a  = B[IDX(t)];
        float2 b  = B[IDX(t + 256)];
        float2 cc = B[IDX(t + 512)];
        float2 dd = B[IDX(t + 768)];
        float2 t0 = cadd(a, cc);
        float2 t1 = csub(a, cc);
        float2 t2 = cadd(b, dd);
        float2 e  = csub(b, dd);
        float2 t3 = make_float2(e.y, -e.x);
        B[IDX(t)]       = cadd(t0, t2);
        B[IDX(t + 256)] = cadd(t1, t3);
        B[IDX(t + 512)] = csub(t0, t2);
        B[IDX(t + 768)] = csub(t1, t3);
    }
    __syncthreads();

    // ---- mags via conjugate pairs ----
    unsigned uv[4][4];
    int      kv[4][4];
    const int k1 = 2 * tid + 1;
    const int k2 = 2 * tid + 2;
#pragma unroll
    for (int cc = 0; cc < 4; cc++) {
        const float2* Z = buf[cc];
        unsigned m0, m1, m2, m3;
        mag_pair(Z, k1, m0, m1);
        mag_pair(Z, k2, m2, m3);
        int b0 = k1, b1 = NH - k1, b2 = k2, b3 = NH - k2;
        if (k2 == 512) { m3 = 0u; }
#define CSWP(a, b, ka, kb) if (a < b) { unsigned tu = a; a = b; b = tu; int tk = ka; ka = kb; kb = tk; }
        CSWP(m0, m1, b0, b1)
        CSWP(m2, m3, b2, b3)
        CSWP(m0, m2, b0, b2)
        CSWP(m1, m3, b1, b3)
        CSWP(m1, m2, b1, b2)
#undef CSWP
        uv[cc][0] = m0; uv[cc][1] = m1; uv[cc][2] = m2; uv[cc][3] = m3;
        kv[cc][0] = b0; kv[cc][1] = b1; kv[cc][2] = b2; kv[cc][3] = b3;
    }

    const int lane = tid & 31;
    const int warp = tid >> 5;
    const unsigned FULL = 0xffffffffu;

    for (int r = 0; r < KSEL; r++) {
#pragma unroll
        for (int cc = 0; cc < 4; cc++) {
            unsigned mx = __reduce_max_sync(FULL, uv[cc][0]);
            unsigned ball = __ballot_sync(FULL, uv[cc][0] == mx);
            int wl = __ffs((int)ball) - 1;
            if (lane == wl) {
                cand_v[cc][warp * KSEL + r] = uv[cc][0];
                cand_k[cc][warp * KSEL + r] = kv[cc][0];
                uv[cc][0] = uv[cc][1]; kv[cc][0] = kv[cc][1];
                uv[cc][1] = uv[cc][2]; kv[cc][1] = kv[cc][2];
                uv[cc][2] = uv[cc][3]; kv[cc][2] = kv[cc][3];
                uv[cc][3] = 0u;
            }
        }
    }
    __syncthreads();

    if (warp < 4) {
        const int cc = warp;
        int ptr = 0, curk = 0;
        unsigned hv = 0u;
        if (lane < 8) { hv = cand_v[cc][lane * KSEL]; curk = cand_k[cc][lane * KSEL]; }
        for (int r = 0; r < KSEL; r++) {
            unsigned mx = __reduce_max_sync(FULL, hv);
            unsigned ball = __ballot_sync(FULL, hv == mx);
            int wl = __ffs((int)ball) - 1;
            int kwin = __shfl_sync(FULL, curk, wl);
            if (lane == 0) sel[cc][r] = kwin;
            if (lane == wl) {
                ptr++;
                if (ptr < KSEL) {
                    hv = cand_v[cc][lane * KSEL + ptr];
                    curk = cand_k[cc][lane * KSEL + ptr];
                } else {
                    hv = 0u;
                }
            }
        }
    }
    __syncthreads();

    // emit into TRANSPOSED layout [b][r][d]; also pre-gather cw/sw/e by k
    if (warp < 4 && lane < KSEL) {
        int k = sel[warp][lane];
        float2 Xk = untangle(buf[warp], k);
        int chan = (blockIdx.x & 127) * 4 + warp;
        int idx = (b4 * KSEL + lane) * DD + chan;
        d_c0[idx]  = Xk.x;
        d_s0[idx]  = Xk.y;
        d_kix[idx] = k;
        d_cw2[idx] = d_cwT[k];
        d_sw2[idx] = d_swT[k];
        d_e2[idx]  = d_eT[k];
    }
}

// ---------------- synthesis: packed-f32x2 Reinsch oscillator --------------
// Coefficient loads fully coalesced via [b][r][d] layout; only rot gathered.
__global__ __launch_bounds__(128, 7) void synth(float* __restrict__ out) {
    const int b  = blockIdx.z;
    const int d  = blockIdx.y * 128 + threadIdx.x;
    const int m  = blockIdx.x;
    const float2* rot = d_rot0 + m * NH;

    float ys[KSEL], dss[KSEL], es[KSEL];
#pragma unroll
    for (int r = 0; r < KSEL; r++) {
        int    idx = (b * KSEL + r) * DD + d;
        int    k   = d_kix[idx];
        float  c0  = d_c0[idx];
        float  s0  = d_s0[idx];
        float  cw  = d_cw2[idx];
        float  sw  = d_sw2[idx];
        float2 rk  = rot[k];
        float  y   = fmaf(c0, rk.x, -s0 * rk.y);     // A cos(theta0)
        float  sn  = fmaf(c0, rk.y,  s0 * rk.x);     // A sin(theta0)
        float  yp  = fmaf(y, cw, sn * sw);           // A cos(theta0 - w)
        ys[r]  = y;
        dss[r] = y - yp;
        es[r]  = d_e2[idx];
    }

    u64 Y[8], D[8], E[8];
#pragma unroll
    for (int p = 0; p < 8; p++) {
        Y[p] = pk(ys[2 * p],  ys[2 * p + 1]);
        D[p] = pk(dss[2 * p], dss[2 * p + 1]);
        E[p] = pk(es[2 * p],  es[2 * p + 1]);
    }

    float* po = out + ((size_t)b * TT_LEN + m * TTILE) * DD + d;
#pragma unroll 4
    for (int tt = 0; tt < TTILE; tt++) {
        u64 q0, q1, q2, q3;
        F2ADD(q0, Y[0], Y[1]);
        F2ADD(q1, Y[2], Y[3]);
        F2ADD(q2, Y[4], Y[5]);
        F2ADD(q3, Y[6], Y[7]);
        F2ADD(q0, q0, q1);
        F2ADD(q2, q2, q3);
        F2ADD(q0, q0, q2);
        float lo, hi;
        upk(q0, lo, hi);
        po[(size_t)tt * DD] = lo + hi;

        // Reinsch advance: D += E*Y ; Y += D
#pragma unroll
        for (int p = 0; p < 8; p++) {
            F2FMA(D[p], E[p], Y[p], D[p]);
            F2ADD(Y[p], Y[p], D[p]);
        }
    }
}

// ---------------- launch ----------------------------------------------------
extern "C" void kernel_launch(void* const* d_in, const int* in_sizes, int n_in,
                              void* d_out, int out_size) {
    const float* x = (const float*)d_in[0];
    float* out = (float*)d_out;

    init_tables<<<47, 256>>>();
    analyze<<<BB * DD / 4, 256>>>(x);
    synth<<<dim3(NM, DD / 128, BB), 128>>>(out);
}